// round 16
// baseline (speedup 1.0000x reference)
#include <cuda_runtime.h>
#include <cuda_bf16.h>
#include <cstdint>

#define N_NODES 100000
#define N_PAD   100352          // 98 * 1024
#define E_MAX   1700000
#define SPAN    1024            // elements per scan block (256 thr * 4)
#define SCAN_BLOCKS 98

// ---------------- scratch (device globals; no allocation allowed) ----------
__device__ float g_P1[N_NODES * 32];
__device__ float g_R1[N_NODES * 32];
__device__ float g_H [N_NODES * 32];
__device__ float g_P2[N_NODES * 32];
__device__ float g_R2[N_NODES * 32];
__device__ int   g_cnt[N_PAD];                       // zero-init; fill_csr drains to 0
__device__ int   g_rowptr[N_NODES + 1];
__device__ int   g_col[E_MAX];
__device__ unsigned long long g_desc[SCAN_BLOCKS];   // lookback descriptors (zero-init)
__device__ unsigned int g_arrive;                    // zero-init; self-reset
__device__ int   g_is64;

// ---------------- edge-index dtype detection (1 warp) ------------------------
__global__ void detect_kernel(const int* __restrict__ ei) {
    cudaGridDependencySynchronize();
    if (threadIdx.x == 0) {
        int allzero = 1;
        #pragma unroll
        for (int j = 1; j < 64; j += 2)
            if (ei[j] != 0) { allzero = 0; break; }
        g_is64 = allzero;
    }
}

// ---------------- CSR build (proven R12 shape) -------------------------------
__global__ void count_edges(const void* __restrict__ ei, int E,
                            int* __restrict__ cnt) {
    cudaGridDependencySynchronize();
    int g = blockIdx.x * blockDim.x + threadIdx.x;
    int e = g * 2;
    if (e >= E) return;
    if (g_is64) {
        const long long* dstb = (const long long*)ei + E;
        if (e + 1 < E) {
            longlong2 d = ((const longlong2*)dstb)[g];
            atomicAdd(cnt + (int)d.x, 1);
            atomicAdd(cnt + (int)d.y, 1);
        } else {
            atomicAdd(cnt + (int)dstb[e], 1);
        }
    } else {
        const int* dstb = (const int*)ei + E;
        if (e + 1 < E) {
            int2 d = ((const int2*)dstb)[g];
            atomicAdd(cnt + d.x, 1);
            atomicAdd(cnt + d.y, 1);
        } else {
            atomicAdd(cnt + dstb[e], 1);
        }
    }
}

// single-pass decoupled-lookback exclusive scan: cnt[0..n) -> rowptr[0..n]
__global__ __launch_bounds__(256)
void scan_lookback(const int* __restrict__ cnt, int* __restrict__ rowptr, int n, int E) {
    cudaGridDependencySynchronize();
    __shared__ int wsum[8];
    __shared__ int s_prefix, s_total;

    const int tid  = threadIdx.x;
    const int wid  = tid >> 5;
    const int lane = tid & 31;
    const int b    = blockIdx.x;
    const int base = b * SPAN + tid * 4;

    int4 v = *(const int4*)(cnt + base);     // padded to N_PAD; tail zeros
    int t0 = v.x;
    int t1 = t0 + v.y;
    int t2 = t1 + v.z;
    int t3 = t2 + v.w;

    int incl = t3;
    #pragma unroll
    for (int o = 1; o < 32; o <<= 1) {
        int t = __shfl_up_sync(0xffffffffu, incl, o);
        if (lane >= o) incl += t;
    }
    if (lane == 31) wsum[wid] = incl;
    __syncthreads();
    if (wid == 0 && lane < 8) {
        int s = wsum[lane];
        int si = s;
        #pragma unroll
        for (int o = 1; o < 8; o <<= 1) {
            int t = __shfl_up_sync(0xffu, si, o);
            if (lane >= o) si += t;
        }
        if (lane == 7) s_total = si;
        wsum[lane] = si - s;
    }
    __syncthreads();
    const int total = s_total;

    volatile unsigned long long* desc = g_desc;
    if (wid == 0) {
        if (b == 0) {
            if (lane == 0) {
                s_prefix = 0;
                desc[0] = ((unsigned long long)total << 2) | 2ull;
            }
        } else {
            if (lane == 0)
                desc[b] = ((unsigned long long)total << 2) | 1ull;
            int prefix = 0;
            int j = b - 1;
            for (;;) {
                int jj = j - lane;
                unsigned long long d = 0;
                if (jj >= 0) {
                    do { d = desc[jj]; } while ((d & 3ull) == 0ull);
                }
                int val = (int)(d >> 2);
                unsigned pf = __ballot_sync(0xffffffffu, jj >= 0 && (d & 3ull) == 2ull);
                if (pf) {
                    int leader = __ffs(pf) - 1;
                    int contrib = (lane <= leader) ? val : 0;
                    #pragma unroll
                    for (int o = 16; o; o >>= 1)
                        contrib += __shfl_xor_sync(0xffffffffu, contrib, o);
                    prefix += contrib;
                    break;
                } else {
                    int contrib = (jj >= 0) ? val : 0;
                    #pragma unroll
                    for (int o = 16; o; o >>= 1)
                        contrib += __shfl_xor_sync(0xffffffffu, contrib, o);
                    prefix += contrib;
                    j -= 32;
                    if (j < 0) break;
                }
            }
            if (lane == 0) {
                s_prefix = prefix;
                desc[b] = ((unsigned long long)(prefix + total) << 2) | 2ull;
            }
        }
    }
    __syncthreads();
    const int bp = s_prefix;

    int off = bp + (incl - t3) + wsum[wid];
    if (base + 3 < n) {
        *(int4*)(rowptr + base) = make_int4(off, off + t0, off + t1, off + t2);
    } else {
        if (base + 0 < n) rowptr[base + 0] = off;
        if (base + 1 < n) rowptr[base + 1] = off + t0;
        if (base + 2 < n) rowptr[base + 2] = off + t1;
        if (base + 3 < n) rowptr[base + 3] = off + t2;
    }
    if (b == SCAN_BLOCKS - 1 && tid == 0) rowptr[n] = bp + total;

    // arrival-gated reset (replay-safe)
    if (tid == 0) {
        if (atomicAdd(&g_arrive, 1u) == SCAN_BLOCKS - 1) {
            for (int i = 0; i < SCAN_BLOCKS; i++) g_desc[i] = 0ull;
            g_arrive = 0u;
        }
    }
}

// cnt[d] holds degree; atomicSub hands out slots and leaves cnt back at 0.
__global__ void fill_csr(const void* __restrict__ ei, int E,
                         const int* __restrict__ rowptr,
                         int* __restrict__ cur, int* __restrict__ col) {
    cudaGridDependencySynchronize();
    int g = blockIdx.x * blockDim.x + threadIdx.x;
    int e = g * 2;
    if (e >= E) return;
    int s0, d0, s1 = 0, d1 = 0;
    bool two = (e + 1 < E);
    if (g_is64) {
        const long long* srcb = (const long long*)ei;
        const long long* dstb = srcb + E;
        if (two) {
            longlong2 sv = ((const longlong2*)srcb)[g];
            longlong2 dv = ((const longlong2*)dstb)[g];
            s0 = (int)sv.x; s1 = (int)sv.y;
            d0 = (int)dv.x; d1 = (int)dv.y;
        } else { s0 = (int)srcb[e]; d0 = (int)dstb[e]; }
    } else {
        const int* srcb = (const int*)ei;
        const int* dstb = srcb + E;
        if (two) {
            int2 sv = ((const int2*)srcb)[g];
            int2 dv = ((const int2*)dstb)[g];
            s0 = sv.x; s1 = sv.y; d0 = dv.x; d1 = dv.y;
        } else { s0 = srcb[e]; d0 = dstb[e]; }
    }
    col[rowptr[d0] + atomicSub(cur + d0, 1) - 1] = s0;
    if (two)
        col[rowptr[d1] + atomicSub(cur + d1, 1) - 1] = s1;
}

// ---------------- tf32 tensor-core dual GEMM: A[M,K] @ [Wl|Wr] --------------
__device__ __forceinline__ uint32_t f2tf32(float f) {
    uint32_t u;
    asm("cvt.rna.tf32.f32 %0, %1;" : "=r"(u) : "f"(f));
    return u;
}

#define LDA_T 20
#define LDW_T 68

template<int K>
__global__ __launch_bounds__(256, 2)
void gemm_tf32(const float* __restrict__ A,
               const float* __restrict__ Wl,
               const float* __restrict__ Wr,
               float* __restrict__ P,
               float* __restrict__ R, int M)
{
    cudaGridDependencySynchronize();
    __shared__ float As[128 * LDA_T];
    __shared__ float Ws[K * LDW_T];

    const int tid  = threadIdx.x;
    const int wid  = tid >> 5;
    const int lane = tid & 31;
    const int row0 = blockIdx.x * 128;

    #pragma unroll
    for (int idx = tid; idx < K * 16; idx += 256) {
        int k  = idx >> 4;
        int j4 = (idx & 15) * 4;
        float4 v = (j4 < 32) ? *(const float4*)(Wl + k * 32 + j4)
                             : *(const float4*)(Wr + k * 32 + (j4 - 32));
        float4 o;
        o.x = __uint_as_float(f2tf32(v.x));
        o.y = __uint_as_float(f2tf32(v.y));
        o.z = __uint_as_float(f2tf32(v.z));
        o.w = __uint_as_float(f2tf32(v.w));
        *(float4*)(Ws + k * LDW_T + j4) = o;
    }

    float acc[8][4] = {};
    const int gr = lane >> 2;
    const int gt = lane & 3;

    for (int kc = 0; kc < K; kc += 16) {
        #pragma unroll
        for (int idx = tid; idx < 128 * 4; idx += 256) {
            int r  = idx >> 2;
            int c4 = (idx & 3) * 4;
            float4 v = make_float4(0.f, 0.f, 0.f, 0.f);
            if (row0 + r < M) v = *(const float4*)(A + (size_t)(row0 + r) * K + kc + c4);
            float4 o;
            o.x = __uint_as_float(f2tf32(v.x));
            o.y = __uint_as_float(f2tf32(v.y));
            o.z = __uint_as_float(f2tf32(v.z));
            o.w = __uint_as_float(f2tf32(v.w));
            *(float4*)(As + r * LDA_T + c4) = o;
        }
        __syncthreads();

        #pragma unroll
        for (int kk = 0; kk < 2; kk++) {
            const uint32_t* asb = (const uint32_t*)As;
            const uint32_t* wsb = (const uint32_t*)Ws;
            int ra = wid * 16 + gr;
            int ca = kk * 8 + gt;
            uint32_t a0 = asb[ra * LDA_T + ca];
            uint32_t a1 = asb[(ra + 8) * LDA_T + ca];
            uint32_t a2 = asb[ra * LDA_T + ca + 4];
            uint32_t a3 = asb[(ra + 8) * LDA_T + ca + 4];
            int kb = kc + kk * 8;
            #pragma unroll
            for (int nt = 0; nt < 8; nt++) {
                uint32_t b0 = wsb[(kb + gt) * LDW_T + nt * 8 + gr];
                uint32_t b1 = wsb[(kb + gt + 4) * LDW_T + nt * 8 + gr];
                asm volatile(
                    "mma.sync.aligned.m16n8k8.row.col.f32.tf32.tf32.f32 "
                    "{%0,%1,%2,%3}, {%4,%5,%6,%7}, {%8,%9}, {%0,%1,%2,%3};"
                    : "+f"(acc[nt][0]), "+f"(acc[nt][1]),
                      "+f"(acc[nt][2]), "+f"(acc[nt][3])
                    : "r"(a0), "r"(a1), "r"(a2), "r"(a3), "r"(b0), "r"(b1));
            }
        }
        __syncthreads();
    }

    int r = row0 + wid * 16 + gr;
    #pragma unroll
    for (int nt = 0; nt < 8; nt++) {
        int colg = nt * 8 + gt * 2;
        float* base = (nt < 4) ? P : R;
        int    c    = (nt < 4) ? colg : colg - 32;
        if (r < M)
            *(float2*)(base + (size_t)r * 32 + c) = make_float2(acc[nt][0], acc[nt][1]);
        if (r + 8 < M)
            *(float2*)(base + (size_t)(r + 8) * 32 + c) = make_float2(acc[nt][2], acc[nt][3]);
    }
}

// ---------------- fused CSR aggregation + mean + bias + relu ----------------
// one warp per node; lane = (q, c): q = edge slot 0..3, c = float4 col 0..7.
// PREDICATED full-width body: always 4 col + 4 data LDGs in flight (MLP=4)
// regardless of degree. Dead slots load col fallback 0 / P row 0 (hot line)
// and are masked out of the accumulation.
__device__ __forceinline__ void f4add(float4& a, const float4& v) {
    a.x += v.x; a.y += v.y; a.z += v.z; a.w += v.w;
}

__global__ __launch_bounds__(256)
void agg_fused(const int* __restrict__ rowptr,
               const int* __restrict__ col,
               const float* __restrict__ P,
               const float* __restrict__ R,
               const float* __restrict__ b,
               float* __restrict__ out)
{
    cudaGridDependencySynchronize();
    int warp = (blockIdx.x * blockDim.x + threadIdx.x) >> 5;
    int lane = threadIdx.x & 31;
    if (warp >= N_NODES) return;

    const int q = lane >> 3;
    const int c = lane & 7;

    int beg = rowptr[warp];
    int end = rowptr[warp + 1];

    float4 a0 = make_float4(0.f, 0.f, 0.f, 0.f);
    float4 a1 = make_float4(0.f, 0.f, 0.f, 0.f);

    for (int i = beg; i < end; i += 16) {
        int e0 = i + q;
        int e1 = e0 + 4;
        int e2 = e0 + 8;
        int e3 = e0 + 12;
        // predicated col loads, fallback index 0 (always a valid P row)
        int s0 = (e0 < end) ? __ldg(col + e0) : 0;
        int s1 = (e1 < end) ? __ldg(col + e1) : 0;
        int s2 = (e2 < end) ? __ldg(col + e2) : 0;
        int s3 = (e3 < end) ? __ldg(col + e3) : 0;
        // unconditional data loads: 4 independent LDG.128 in flight
        float4 v0 = __ldg((const float4*)(P + (size_t)s0 * 32) + c);
        float4 v1 = __ldg((const float4*)(P + (size_t)s1 * 32) + c);
        float4 v2 = __ldg((const float4*)(P + (size_t)s2 * 32) + c);
        float4 v3 = __ldg((const float4*)(P + (size_t)s3 * 32) + c);
        if (e0 < end) f4add(a0, v0);
        if (e1 < end) f4add(a1, v1);
        if (e2 < end) f4add(a0, v2);
        if (e3 < end) f4add(a1, v3);
    }
    f4add(a0, a1);

    #pragma unroll
    for (int o = 8; o <= 16; o <<= 1) {
        a0.x += __shfl_xor_sync(0xffffffffu, a0.x, o);
        a0.y += __shfl_xor_sync(0xffffffffu, a0.y, o);
        a0.z += __shfl_xor_sync(0xffffffffu, a0.z, o);
        a0.w += __shfl_xor_sync(0xffffffffu, a0.w, o);
    }

    if (q == 0) {
        float invd = 1.0f / fmaxf((float)(end - beg), 1.0f);
        float4 r  = __ldg((const float4*)(R + (size_t)warp * 32) + c);
        float4 bb = __ldg((const float4*)b + c);
        float4 o;
        o.x = fmaxf(fmaf(a0.x, invd, bb.x) + r.x, 0.f);
        o.y = fmaxf(fmaf(a0.y, invd, bb.y) + r.y, 0.f);
        o.z = fmaxf(fmaf(a0.z, invd, bb.z) + r.z, 0.f);
        o.w = fmaxf(fmaf(a0.w, invd, bb.w) + r.w, 0.f);
        *((float4*)(out + (size_t)warp * 32) + c) = o;
    }
}

// ---------------- PDL launch helper (any stream) -----------------------------
template<typename F, typename... Args>
static inline void launch_pdl_s(cudaStream_t st, F* k, dim3 grid, dim3 block, Args... args) {
    cudaLaunchConfig_t cfg = {};
    cfg.gridDim  = grid;
    cfg.blockDim = block;
    cfg.dynamicSmemBytes = 0;
    cfg.stream = st;
    cudaLaunchAttribute at[1];
    at[0].id = cudaLaunchAttributeProgrammaticStreamSerialization;
    at[0].val.programmaticStreamSerializationAllowed = 1;
    cfg.attrs = at;
    cfg.numAttrs = 1;
    cudaLaunchKernelEx(&cfg, k, args...);
}

// ---------------- launcher --------------------------------------------------
extern "C" void kernel_launch(void* const* d_in, const int* in_sizes, int n_in,
                              void* d_out, int out_size)
{
    const float* x   = (const float*)d_in[0];
    const void*  ei  = d_in[1];
    const float* W1l = (const float*)d_in[2];
    const float* b1l = (const float*)d_in[3];
    const float* W1r = (const float*)d_in[4];
    const float* W2l = (const float*)d_in[5];
    const float* b2l = (const float*)d_in[6];
    const float* W2r = (const float*)d_in[7];
    float* out = (float*)d_out;

    const int E = in_sizes[1] / 2;
    const int M = N_NODES;

    float *P1, *R1, *H, *P2, *R2;
    int *cnt, *rowptr, *colA;
    cudaGetSymbolAddress((void**)&P1,     g_P1);
    cudaGetSymbolAddress((void**)&R1,     g_R1);
    cudaGetSymbolAddress((void**)&H,      g_H);
    cudaGetSymbolAddress((void**)&P2,     g_P2);
    cudaGetSymbolAddress((void**)&R2,     g_R2);
    cudaGetSymbolAddress((void**)&cnt,    g_cnt);
    cudaGetSymbolAddress((void**)&rowptr, g_rowptr);
    cudaGetSymbolAddress((void**)&colA,   g_col);

    static cudaStream_t s_side = [](){
        cudaStream_t s; cudaStreamCreateWithFlags(&s, cudaStreamNonBlocking); return s;
    }();
    static cudaEvent_t s_evFork = [](){
        cudaEvent_t e; cudaEventCreateWithFlags(&e, cudaEventDisableTiming); return e;
    }();
    static cudaEvent_t s_evCSR = [](){
        cudaEvent_t e; cudaEventCreateWithFlags(&e, cudaEventDisableTiming); return e;
    }();

    const int pair_blocks = (E / 2 + 256) / 256;   // 2 edges per thread
    const int agg_blocks  = (M * 32 + 255) / 256;

    // stream 0 position 0: detect
    launch_pdl_s(0, detect_kernel, dim3(1), dim3(32), (const int*)ei);
    cudaEventRecord(s_evFork, 0);

    // CSR build chain on SIDE stream (overlaps gemm1 on stream 0)
    cudaStreamWaitEvent(s_side, s_evFork, 0);
    launch_pdl_s(s_side, count_edges, dim3(pair_blocks), dim3(256), ei, E, cnt);
    launch_pdl_s(s_side, scan_lookback, dim3(SCAN_BLOCKS), dim3(256), (const int*)cnt, rowptr, M, E);
    launch_pdl_s(s_side, fill_csr, dim3(pair_blocks), dim3(256), ei, E, (const int*)rowptr, cnt, colA);
    cudaEventRecord(s_evCSR, s_side);

    // stream 0: gemm1 (overlaps CSR chain)
    launch_pdl_s(0, gemm_tf32<128>, dim3((M + 127) / 128), dim3(256),
                 x, W1l, W1r, P1, R1, M);

    // join: agg1 needs CSR (side) and P1/R1 (stream 0 program order)
    cudaStreamWaitEvent(0, s_evCSR, 0);

    launch_pdl_s(0, agg_fused, dim3(agg_blocks), dim3(256),
                 (const int*)rowptr, (const int*)colA,
                 (const float*)P1, (const float*)R1, b1l, H);
    launch_pdl_s(0, gemm_tf32<32>, dim3((M + 127) / 128), dim3(256),
                 (const float*)H, W2l, W2r, P2, R2, M);
    launch_pdl_s(0, agg_fused, dim3(agg_blocks), dim3(256),
                 (const int*)rowptr, (const int*)colA,
                 (const float*)P2, (const float*)R2, b2l, out);
}

// round 17
// speedup vs baseline: 1.4965x; 1.4965x over previous
#include <cuda_runtime.h>
#include <cuda_bf16.h>
#include <cstdint>

#define N_NODES 100000
#define E_MAX   1700000
#define SCAN_B  256

// ---------------- scratch (device globals; no allocation allowed) ----------
__device__ float g_P1[N_NODES * 32];
__device__ float g_R1[N_NODES * 32];
__device__ float g_H [N_NODES * 32];
__device__ float g_P2[N_NODES * 32];
__device__ float g_R2[N_NODES * 32];
__device__ int   g_cnt[N_NODES];
__device__ int   g_rowptr[N_NODES + 1];
__device__ int   g_col[E_MAX];
__device__ int   g_bsums[512];
__device__ int   g_is64;

// ---------------- zero cnt + edge-index dtype detection ---------------------
__global__ void zero_and_detect(int* __restrict__ cnt, const int* __restrict__ ei) {
    cudaGridDependencySynchronize();
    int i = blockIdx.x * blockDim.x + threadIdx.x;
    if (i < N_NODES) cnt[i] = 0;
    if (i == 0) {
        int allzero = 1;
        #pragma unroll
        for (int j = 1; j < 64; j += 2)
            if (ei[j] != 0) { allzero = 0; break; }
        g_is64 = allzero;
    }
}

__device__ __forceinline__ int load_idx(const void* ei, long long i) {
    return g_is64 ? (int)((const long long*)ei)[i] : ((const int*)ei)[i];
}

// ---------------- CSR build --------------------------------------------------
__global__ void count_edges(const void* __restrict__ ei, int E,
                            int* __restrict__ cnt) {
    cudaGridDependencySynchronize();
    int e = blockIdx.x * blockDim.x + threadIdx.x;
    if (e >= E) return;
    atomicAdd(cnt + load_idx(ei, (long long)E + e), 1);
}

// warp-shuffle block scan (exclusive out), SCAN_B = 256 threads
__global__ void scan_blocks(const int* __restrict__ cnt,
                            int* __restrict__ rowptr,
                            int* __restrict__ bsums, int n) {
    cudaGridDependencySynchronize();
    __shared__ int wsum[8];
    int tid  = threadIdx.x;
    int wid  = tid >> 5;
    int lane = tid & 31;
    int i = blockIdx.x * SCAN_B + tid;
    int v = (i < n) ? cnt[i] : 0;

    int incl = v;
    #pragma unroll
    for (int o = 1; o < 32; o <<= 1) {
        int t = __shfl_up_sync(0xffffffffu, incl, o);
        if (lane >= o) incl += t;
    }
    if (lane == 31) wsum[wid] = incl;
    __syncthreads();
    if (wid == 0 && lane < 8) {
        int s = wsum[lane];
        int si = s;
        #pragma unroll
        for (int o = 1; o < 8; o <<= 1) {
            int t = __shfl_up_sync(0xffu, si, o);
            if (lane >= o) si += t;
        }
        wsum[lane] = si - s;
    }
    __syncthreads();
    incl += wsum[wid];
    if (i < n) rowptr[i] = incl - v;
    if (tid == SCAN_B - 1) bsums[blockIdx.x] = incl;
}

// each block computes its own bsums prefix with one warp, then offsets rows
__global__ void add_offsets(int* __restrict__ rowptr,
                            const int* __restrict__ bsums, int n, int E) {
    cudaGridDependencySynchronize();
    __shared__ int carry;
    int b = blockIdx.x;
    if (threadIdx.x < 32) {
        int sum = 0;
        for (int j = (int)threadIdx.x; j < b; j += 32) sum += bsums[j];
        #pragma unroll
        for (int o = 16; o; o >>= 1) sum += __shfl_xor_sync(0xffffffffu, sum, o);
        if (threadIdx.x == 0) carry = sum;
    }
    __syncthreads();
    int i = b * SCAN_B + threadIdx.x;
    if (i < n) rowptr[i] += carry;
    if (i == 0) rowptr[n] = E;
}

// cnt[d] holds degree; atomicSub hands out slots and leaves cnt back at 0
__global__ void fill_csr(const void* __restrict__ ei, int E,
                         const int* __restrict__ rowptr,
                         int* __restrict__ cur, int* __restrict__ col) {
    cudaGridDependencySynchronize();
    int e = blockIdx.x * blockDim.x + threadIdx.x;
    if (e >= E) return;
    int s = load_idx(ei, e);
    int d = load_idx(ei, (long long)E + e);
    col[rowptr[d] + atomicSub(cur + d, 1) - 1] = s;
}

// ---------------- tf32 tensor-core dual GEMM: A[M,K] @ [Wl|Wr] --------------
__device__ __forceinline__ uint32_t f2tf32(float f) {
    uint32_t u;
    asm("cvt.rna.tf32.f32 %0, %1;" : "=r"(u) : "f"(f));
    return u;
}

#define LDA_T 20
#define LDW_T 68

template<int K>
__global__ __launch_bounds__(256, 2)
void gemm_tf32(const float* __restrict__ A,
               const float* __restrict__ Wl,
               const float* __restrict__ Wr,
               float* __restrict__ P,
               float* __restrict__ R, int M)
{
    cudaGridDependencySynchronize();
    __shared__ float As[128 * LDA_T];
    __shared__ float Ws[K * LDW_T];

    const int tid  = threadIdx.x;
    const int wid  = tid >> 5;
    const int lane = tid & 31;
    const int row0 = blockIdx.x * 128;

    #pragma unroll
    for (int idx = tid; idx < K * 16; idx += 256) {
        int k  = idx >> 4;
        int j4 = (idx & 15) * 4;
        float4 v = (j4 < 32) ? *(const float4*)(Wl + k * 32 + j4)
                             : *(const float4*)(Wr + k * 32 + (j4 - 32));
        float4 o;
        o.x = __uint_as_float(f2tf32(v.x));
        o.y = __uint_as_float(f2tf32(v.y));
        o.z = __uint_as_float(f2tf32(v.z));
        o.w = __uint_as_float(f2tf32(v.w));
        *(float4*)(Ws + k * LDW_T + j4) = o;
    }

    float acc[8][4] = {};
    const int gr = lane >> 2;
    const int gt = lane & 3;

    for (int kc = 0; kc < K; kc += 16) {
        #pragma unroll
        for (int idx = tid; idx < 128 * 4; idx += 256) {
            int r  = idx >> 2;
            int c4 = (idx & 3) * 4;
            float4 v = make_float4(0.f, 0.f, 0.f, 0.f);
            if (row0 + r < M) v = *(const float4*)(A + (size_t)(row0 + r) * K + kc + c4);
            float4 o;
            o.x = __uint_as_float(f2tf32(v.x));
            o.y = __uint_as_float(f2tf32(v.y));
            o.z = __uint_as_float(f2tf32(v.z));
            o.w = __uint_as_float(f2tf32(v.w));
            *(float4*)(As + r * LDA_T + c4) = o;
        }
        __syncthreads();

        #pragma unroll
        for (int kk = 0; kk < 2; kk++) {
            const uint32_t* asb = (const uint32_t*)As;
            const uint32_t* wsb = (const uint32_t*)Ws;
            int ra = wid * 16 + gr;
            int ca = kk * 8 + gt;
            uint32_t a0 = asb[ra * LDA_T + ca];
            uint32_t a1 = asb[(ra + 8) * LDA_T + ca];
            uint32_t a2 = asb[ra * LDA_T + ca + 4];
            uint32_t a3 = asb[(ra + 8) * LDA_T + ca + 4];
            int kb = kc + kk * 8;
            #pragma unroll
            for (int nt = 0; nt < 8; nt++) {
                uint32_t b0 = wsb[(kb + gt) * LDW_T + nt * 8 + gr];
                uint32_t b1 = wsb[(kb + gt + 4) * LDW_T + nt * 8 + gr];
                asm volatile(
                    "mma.sync.aligned.m16n8k8.row.col.f32.tf32.tf32.f32 "
                    "{%0,%1,%2,%3}, {%4,%5,%6,%7}, {%8,%9}, {%0,%1,%2,%3};"
                    : "+f"(acc[nt][0]), "+f"(acc[nt][1]),
                      "+f"(acc[nt][2]), "+f"(acc[nt][3])
                    : "r"(a0), "r"(a1), "r"(a2), "r"(a3), "r"(b0), "r"(b1));
            }
        }
        __syncthreads();
    }

    int r = row0 + wid * 16 + gr;
    #pragma unroll
    for (int nt = 0; nt < 8; nt++) {
        int colg = nt * 8 + gt * 2;
        float* base = (nt < 4) ? P : R;
        int    c    = (nt < 4) ? colg : colg - 32;
        if (r < M)
            *(float2*)(base + (size_t)r * 32 + c) = make_float2(acc[nt][0], acc[nt][1]);
        if (r + 8 < M)
            *(float2*)(base + (size_t)(r + 8) * 32 + c) = make_float2(acc[nt][2], acc[nt][3]);
    }
}

// ---------------- fused CSR aggregation + mean + bias + relu (float4) -------
// one warp per node; lane = (q, c): q = edge slot 0..3, c = float4 col 0..7
__device__ __forceinline__ void f4add(float4& a, const float4& v) {
    a.x += v.x; a.y += v.y; a.z += v.z; a.w += v.w;
}

__global__ __launch_bounds__(128)
void agg_fused(const int* __restrict__ rowptr,
               const int* __restrict__ col,
               const float* __restrict__ P,
               const float* __restrict__ R,
               const float* __restrict__ b,
               float* __restrict__ out)
{
    cudaGridDependencySynchronize();
    int warp = (blockIdx.x * blockDim.x + threadIdx.x) >> 5;
    int lane = threadIdx.x & 31;
    if (warp >= N_NODES) return;

    const int q = lane >> 3;
    const int c = lane & 7;

    int beg = rowptr[warp];
    int end = rowptr[warp + 1];

    float4 a0 = make_float4(0.f, 0.f, 0.f, 0.f);
    float4 a1 = make_float4(0.f, 0.f, 0.f, 0.f);

    int i = beg;
    for (; i + 16 <= end; i += 16) {
        int s0 = __ldg(col + i +      q);
        int s1 = __ldg(col + i +  4 + q);
        int s2 = __ldg(col + i +  8 + q);
        int s3 = __ldg(col + i + 12 + q);
        float4 v0 = __ldg((const float4*)(P + (size_t)s0 * 32) + c);
        float4 v1 = __ldg((const float4*)(P + (size_t)s1 * 32) + c);
        float4 v2 = __ldg((const float4*)(P + (size_t)s2 * 32) + c);
        float4 v3 = __ldg((const float4*)(P + (size_t)s3 * 32) + c);
        f4add(a0, v0); f4add(a1, v1); f4add(a0, v2); f4add(a1, v3);
    }
    if (i + 8 <= end) {
        int s0 = __ldg(col + i +     q);
        int s1 = __ldg(col + i + 4 + q);
        float4 v0 = __ldg((const float4*)(P + (size_t)s0 * 32) + c);
        float4 v1 = __ldg((const float4*)(P + (size_t)s1 * 32) + c);
        f4add(a0, v0); f4add(a1, v1);
        i += 8;
    }
    for (; i < end; i += 4) {
        int e = i + q;
        if (e < end) {
            int s = __ldg(col + e);
            float4 v = __ldg((const float4*)(P + (size_t)s * 32) + c);
            f4add(a0, v);
        }
    }
    f4add(a0, a1);

    #pragma unroll
    for (int o = 8; o <= 16; o <<= 1) {
        a0.x += __shfl_xor_sync(0xffffffffu, a0.x, o);
        a0.y += __shfl_xor_sync(0xffffffffu, a0.y, o);
        a0.z += __shfl_xor_sync(0xffffffffu, a0.z, o);
        a0.w += __shfl_xor_sync(0xffffffffu, a0.w, o);
    }

    if (q == 0) {
        float invd = 1.0f / fmaxf((float)(end - beg), 1.0f);
        float4 r  = __ldg((const float4*)(R + (size_t)warp * 32) + c);
        float4 bb = __ldg((const float4*)b + c);
        float4 o;
        o.x = fmaxf(fmaf(a0.x, invd, bb.x) + r.x, 0.f);
        o.y = fmaxf(fmaf(a0.y, invd, bb.y) + r.y, 0.f);
        o.z = fmaxf(fmaf(a0.z, invd, bb.z) + r.z, 0.f);
        o.w = fmaxf(fmaf(a0.w, invd, bb.w) + r.w, 0.f);
        *((float4*)(out + (size_t)warp * 32) + c) = o;
    }
}

// ---------------- PDL launch helper -----------------------------------------
template<typename F, typename... Args>
static inline void launch_pdl(F* k, dim3 grid, dim3 block, Args... args) {
    cudaLaunchConfig_t cfg = {};
    cfg.gridDim  = grid;
    cfg.blockDim = block;
    cfg.dynamicSmemBytes = 0;
    cfg.stream = 0;
    cudaLaunchAttribute at[1];
    at[0].id = cudaLaunchAttributeProgrammaticStreamSerialization;
    at[0].val.programmaticStreamSerializationAllowed = 1;
    cfg.attrs = at;
    cfg.numAttrs = 1;
    cudaLaunchKernelEx(&cfg, k, args...);
}

// ---------------- launcher --------------------------------------------------
extern "C" void kernel_launch(void* const* d_in, const int* in_sizes, int n_in,
                              void* d_out, int out_size)
{
    const float* x   = (const float*)d_in[0];
    const void*  ei  = d_in[1];
    const float* W1l = (const float*)d_in[2];
    const float* b1l = (const float*)d_in[3];
    const float* W1r = (const float*)d_in[4];
    const float* W2l = (const float*)d_in[5];
    const float* b2l = (const float*)d_in[6];
    const float* W2r = (const float*)d_in[7];
    float* out = (float*)d_out;

    const int E = in_sizes[1] / 2;
    const int M = N_NODES;

    float *P1, *R1, *H, *P2, *R2;
    int *cnt, *rowptr, *colA, *bsums;
    cudaGetSymbolAddress((void**)&P1,     g_P1);
    cudaGetSymbolAddress((void**)&R1,     g_R1);
    cudaGetSymbolAddress((void**)&H,      g_H);
    cudaGetSymbolAddress((void**)&P2,     g_P2);
    cudaGetSymbolAddress((void**)&R2,     g_R2);
    cudaGetSymbolAddress((void**)&cnt,    g_cnt);
    cudaGetSymbolAddress((void**)&rowptr, g_rowptr);
    cudaGetSymbolAddress((void**)&colA,   g_col);
    cudaGetSymbolAddress((void**)&bsums,  g_bsums);

    static cudaStream_t s_side = [](){
        cudaStream_t s; cudaStreamCreateWithFlags(&s, cudaStreamNonBlocking); return s;
    }();
    static cudaEvent_t s_evFork = [](){
        cudaEvent_t e; cudaEventCreateWithFlags(&e, cudaEventDisableTiming); return e;
    }();
    static cudaEvent_t s_evJoin = [](){
        cudaEvent_t e; cudaEventCreateWithFlags(&e, cudaEventDisableTiming); return e;
    }();

    const int edge_blocks   = (E + 255) / 256;
    const int scan_blocks_n = (M + SCAN_B - 1) / SCAN_B;
    const int agg_blocks    = (M * 32 + 127) / 128;   // 128-thread agg blocks

    // fork: gemm1 runs on side stream concurrently with CSR build
    cudaEventRecord(s_evFork, 0);
    cudaStreamWaitEvent(s_side, s_evFork, 0);
    gemm_tf32<128><<<(M + 127) / 128, 256, 0, s_side>>>(x, W1l, W1r, P1, R1, M);
    cudaEventRecord(s_evJoin, s_side);

    // CSR build chain on stream 0 (PDL-serialized)
    launch_pdl(zero_and_detect, dim3((M + 1023) / 1024), dim3(1024), cnt, (const int*)ei);
    launch_pdl(count_edges, dim3(edge_blocks), dim3(256), ei, E, cnt);
    launch_pdl(scan_blocks, dim3(scan_blocks_n), dim3(SCAN_B), (const int*)cnt, rowptr, bsums, M);
    launch_pdl(add_offsets, dim3(scan_blocks_n), dim3(SCAN_B), rowptr, (const int*)bsums, M, E);
    launch_pdl(fill_csr, dim3(edge_blocks), dim3(256), ei, E, (const int*)rowptr, cnt, colA);

    // join: agg1 needs both CSR (stream 0) and P1/R1 (side stream)
    cudaStreamWaitEvent(0, s_evJoin, 0);

    launch_pdl(agg_fused, dim3(agg_blocks), dim3(128),
               (const int*)rowptr, (const int*)colA,
               (const float*)P1, (const float*)R1, b1l, H);
    launch_pdl(gemm_tf32<32>, dim3((M + 127) / 128), dim3(256),
               (const float*)H, W2l, W2r, P2, R2, M);
    launch_pdl(agg_fused, dim3(agg_blocks), dim3(128),
               (const int*)rowptr, (const int*)colA,
               (const float*)P2, (const float*)R2, b2l, out);
}